// round 17
// baseline (speedup 1.0000x reference)
#include <cuda_runtime.h>
#include <math.h>
#include <stdint.h>

typedef unsigned long long ull;

// Problem constants: B=4, L=1024, H=512, NH=8, HD=64, rel rows = 2048

__device__ float g_rel[2048 * 64];            // rel[t][d]
__device__ float g_relD[8 * 2048];            // delta_n . rel_t
__device__ float g_q[4 * 8 * 1024 * 64];      // [b][n][l][d]
__device__ float g_v[4 * 8 * 1024 * 64];

// ---------------------------------------------------------------------------
// Packed fp32x2 helpers (FFMA2)
// ---------------------------------------------------------------------------
__device__ __forceinline__ ull fma2(ull a, ull b, ull c) {
    ull d;
    asm("fma.rn.f32x2 %0, %1, %2, %3;" : "=l"(d) : "l"(a), "l"(b), "l"(c));
    return d;
}
__device__ __forceinline__ ull mul2(ull a, ull b) {
    ull d;
    asm("mul.rn.f32x2 %0, %1, %2;" : "=l"(d) : "l"(a), "l"(b));
    return d;
}
__device__ __forceinline__ ull pack2(float x, float y) {
    ull d;
    asm("mov.b64 %0, {%1, %2};" : "=l"(d) : "f"(x), "f"(y));
    return d;
}
__device__ __forceinline__ float2 unpack2(ull a) {
    float x, y;
    asm("mov.b64 {%0, %1}, %2;" : "=f"(x), "=f"(y) : "l"(a));
    return make_float2(x, y);
}
// cp.async helpers
__device__ __forceinline__ void cp8(uint32_t dst, const void* src) {
    asm volatile("cp.async.ca.shared.global [%0], [%1], 8;" :: "r"(dst), "l"(src));
}
__device__ __forceinline__ void cp16(uint32_t dst, const void* src) {
    asm volatile("cp.async.cg.shared.global [%0], [%1], 16;" :: "r"(dst), "l"(src));
}
__device__ __forceinline__ void cp_commit() {
    asm volatile("cp.async.commit_group;" ::: "memory");
}
__device__ __forceinline__ void cp_wait0() {
    asm volatile("cp.async.wait_group 0;" ::: "memory");
}

// ---------------------------------------------------------------------------
// Kernel 1: rel[t][d] = emb(t) @ w_r_w + w_r_b   (R15 verbatim, proven)
// ---------------------------------------------------------------------------
__global__ void __launch_bounds__(256) rel_kernel(const float* __restrict__ w_r_w,
                                                  const float* __restrict__ w_r_b) {
    extern __shared__ float rsm[];
    float* Wsm = rsm;            // 512*64
    float* Emb = Wsm + 32768;    // 8*512

    const int tid = threadIdx.x;
    const int r0 = blockIdx.x * 8;
    const float cc = (float)(-9.210340371976184 / 255.0);

    for (int idx = tid * 4; idx < 32768; idx += 1024)
        *(float4*)&Wsm[idx] = *(const float4*)&w_r_w[idx];

    for (int idx = tid; idx < 8 * 512; idx += 256) {
        int row = idx >> 9;
        int h = idx & 511;
        int t = (h < 256) ? h : (h - 256);
        float f = expf((float)t * cc);
        float ang = (float)(r0 + row - 1024) * f;
        Emb[idx] = (h < 256) ? sinf(ang) : cosf(ang);
    }
    __syncthreads();

    const int d = tid & 63;
    const int rl = tid >> 6;
    const float bias = w_r_b[d];
    #pragma unroll
    for (int rr = 0; rr < 2; rr++) {
        int row = rl + 4 * rr;
        float sum = bias;
        const float* e = &Emb[row * 512];
        #pragma unroll 8
        for (int h = 0; h < 512; h++)
            sum = fmaf(e[h], Wsm[h * 64 + d], sum);
        g_rel[(size_t)(r0 + row) * 64 + d] = sum;
    }
}

// ---------------------------------------------------------------------------
// Kernel 1b: g_relD[n][t] = (r_w_bias[n] - r_r_bias[n]) . g_rel[t]  (proven)
// ---------------------------------------------------------------------------
__global__ void __launch_bounds__(256) reld_kernel(const float* __restrict__ rr_bias,
                                                   const float* __restrict__ rw_bias) {
    __shared__ float relS[32 * 64];
    __shared__ float dS[8 * 64];
    const int tid = threadIdx.x;
    const int t0 = blockIdx.x * 32;

    for (int i = tid; i < 512; i += 256)
        dS[i] = rw_bias[i] - rr_bias[i];
    for (int i = tid * 4; i < 2048; i += 1024)
        *(float4*)&relS[i] = *(const float4*)&g_rel[(size_t)t0 * 64 + i];
    __syncthreads();

    const int tl = tid >> 3, n = tid & 7;
    const float* dn = &dS[n * 64];
    const float* rrow = &relS[tl * 64];
    float s = 0.f;
    #pragma unroll 16
    for (int d = 0; d < 64; d++)
        s = fmaf(dn[d], rrow[d], s);
    g_relD[n * 2048 + t0 + tl] = s;
}

// ---------------------------------------------------------------------------
// Kernel 2: projections, FFMA2, SIMPLE (static smem, sync loads, single buf).
// 128x128 tile, 256 thr; thread (tx,ty) owns rows ty+16r (r<8),
// cols tx*8 + 2p..2p+1 (p<4).
// ---------------------------------------------------------------------------
__global__ void __launch_bounds__(256) proj2_kernel(
    const float* __restrict__ q_in, const float* __restrict__ v_in,
    const float* __restrict__ wq, const float* __restrict__ bq,
    const float* __restrict__ wv, const float* __restrict__ bv) {

    __shared__ float As[128 * 36];   // [m][k], k pad to 36
    __shared__ float Bs[32 * 132];   // [k][n], n pad to 132

    const bool isv = (blockIdx.z != 0);
    const float* X    = isv ? v_in : q_in;
    const float* W    = isv ? wv : wq;
    const float* bias = isv ? bv : bq;
    float* out        = isv ? g_v : g_q;

    const int tid = threadIdx.x;
    const int tx = tid & 15, ty = tid >> 4;
    const int m0 = blockIdx.x * 128;   // 32 m-tiles
    const int n0 = blockIdx.y * 128;   // 4 n-tiles

    ull acc2[8][4];
    #pragma unroll
    for (int r = 0; r < 8; r++)
        #pragma unroll
        for (int p = 0; p < 4; p++) acc2[r][p] = 0ULL;

    for (int kc = 0; kc < 16; kc++) {
        const int k0 = kc * 32;
        if (kc) __syncthreads();     // prior compute done before overwrite
        // A: 128 rows x 32 k (8 float4 per row)
        #pragma unroll
        for (int i = 0; i < 4; i++) {
            int idx = tid + i * 256;           // 0..1023
            int m = idx >> 3, c4 = (idx & 7) * 4;
            float4 v = *(const float4*)&X[(size_t)(m0 + m) * 512 + k0 + c4];
            *(float4*)&As[m * 36 + c4] = v;
        }
        // B: 32 k-rows x 128 n (32 float4 per row)
        #pragma unroll
        for (int i = 0; i < 4; i++) {
            int idx = tid + i * 256;
            int k = idx >> 5, c4 = (idx & 31) * 4;
            float4 v = *(const float4*)&W[(size_t)(k0 + k) * 512 + n0 + c4];
            *(float4*)&Bs[k * 132 + c4] = v;
        }
        __syncthreads();

        const float* pA = As + ty * 36;        // + r*576 + k
        const float* pB = Bs + tx * 8;         // + k*132 + 2p
        #pragma unroll 4
        for (int k = 0; k < 32; k++) {
            ull a2[8], b2[4];
            #pragma unroll
            for (int r = 0; r < 8; r++) {
                float a = pA[r * 576 + k];
                a2[r] = pack2(a, a);
            }
            #pragma unroll
            for (int p = 0; p < 4; p++)
                b2[p] = *(const ull*)&pB[k * 132 + 2 * p];
            #pragma unroll
            for (int r = 0; r < 8; r++)
                #pragma unroll
                for (int p = 0; p < 4; p++)
                    acc2[r][p] = fma2(a2[r], b2[p], acc2[r][p]);
        }
    }

    // epilogue: rows m0+ty+16r; cols n0+tx*8..+7 (within one head)
    const int ncol = n0 + tx * 8;
    const int head = ncol >> 6, d0 = ncol & 63;
    float bb[8];
    #pragma unroll
    for (int i = 0; i < 8; i++) bb[i] = bias[ncol + i];

    #pragma unroll
    for (int r = 0; r < 8; r++) {
        int m = m0 + ty + 16 * r;
        int b = m >> 10, l = m & 1023;
        float2 v0 = unpack2(acc2[r][0]);
        float2 v1 = unpack2(acc2[r][1]);
        float2 v2 = unpack2(acc2[r][2]);
        float2 v3 = unpack2(acc2[r][3]);
        float* dst = &out[(size_t)((b * 8 + head) * 1024 + l) * 64 + d0];
        float4 o0, o1;
        o0.x = v0.x + bb[0]; o0.y = v0.y + bb[1];
        o0.z = v1.x + bb[2]; o0.w = v1.y + bb[3];
        o1.x = v2.x + bb[4]; o1.y = v2.y + bb[5];
        o1.z = v3.x + bb[6]; o1.w = v3.y + bb[7];
        *(float4*)&dst[0] = o0;
        *(float4*)&dst[4] = o1;
    }
}

// ---------------------------------------------------------------------------
// Kernel 3: fused attention (R15 verbatim, proven).
// ---------------------------------------------------------------------------
__global__ void __launch_bounds__(256, 1) attn_kernel(
    const float* __restrict__ key,
    const float* __restrict__ r_r_bias,
    const int*   __restrict__ seq_len_p,
    float* __restrict__ out) {

    extern __shared__ float sm[];
    float* QA  = sm;                 // 128 x 66          [0,     8448)
    float* Ks  = QA + 8448;          //  64 x 66          [8448, 12672)
    float* Pm  = Ks + 4224;          // 128 x 66          [12672,21120)
    float* RB  = Pm + 8448;          // 192 x 66          [21120,33792)
    float* RE  = RB + 12672;         // 192 x 66          [33792,46464)
    float* Vs0 = RE + 12672;         //  64 x 64          [46464,50560)
    float* Vs1 = Vs0 + 4096;         //  64 x 64          [50560,54656)

    const int tid = threadIdx.x;
    const int tx = tid & 15, ty = tid >> 4;
    const int tx4 = tx * 4;
    const int i0 = blockIdx.x * 128;
    const int bn = blockIdx.y;
    const int b = bn >> 3, n = bn & 7;
    const int seq = *seq_len_p;

    const float* qptr = g_q + (size_t)bn * 1024 * 64;
    const float* vptr = g_v + (size_t)bn * 1024 * 64;
    const float* kptr = key + (size_t)b * 1024 * 512 + n * 64;
    const float* relD = g_relD + n * 2048;

    const uint32_t ksA  = (uint32_t)__cvta_generic_to_shared(Ks);
    const uint32_t rbA  = (uint32_t)__cvta_generic_to_shared(RB);
    const uint32_t reA  = (uint32_t)__cvta_generic_to_shared(RE);
    const uint32_t vs0A = (uint32_t)__cvta_generic_to_shared(Vs0);
    const uint32_t vs1A = (uint32_t)__cvta_generic_to_shared(Vs1);

    auto load_tiles = [&](int j0n, uint32_t vsDst) {
        for (int idx = tid; idx < 2048; idx += 256) {
            int j = idx >> 5, ch = idx & 31;
            cp8(ksA + (uint32_t)(j * 66 + ch * 2) * 4,
                kptr + (size_t)(j0n + j) * 512 + ch * 2);
        }
        for (int idx = tid; idx < 1024; idx += 256) {
            int j = idx >> 4, ch = idx & 15;
            cp16(vsDst + (uint32_t)(j * 64 + ch * 4) * 4,
                 vptr + (size_t)(j0n + j) * 64 + ch * 4);
        }
        const int rbBase = 1024 + j0n - i0 - 127;
        const int reBase = 1024 + i0 - j0n - 63;
        for (int idx = tid; idx < 6144; idx += 256) {
            int u = idx >> 5, ch = idx & 31;
            int rb_r = rbBase + u; rb_r = (rb_r > 2047) ? 2047 : rb_r;
            cp8(rbA + (uint32_t)(u * 66 + ch * 2) * 4,
                g_rel + (size_t)rb_r * 64 + ch * 2);
        }
        for (int idx = tid; idx < 6144; idx += 256) {
            int u = idx >> 5, ch = idx & 31;
            int re_r = reBase + u; re_r = (re_r > 2047) ? 2047 : re_r;
            cp8(reA + (uint32_t)(u * 66 + ch * 2) * 4,
                g_rel + (size_t)re_r * 64 + ch * 2);
        }
    };

    // QA = q + r_r_bias  (128 rows)
    for (int idx = tid; idx < 2048; idx += 256) {
        int i = idx >> 4; int d4 = (idx & 15) << 2;
        float4 q4 = *(const float4*)&qptr[(size_t)(i0 + i) * 64 + d4];
        float4 rr = *(const float4*)&r_r_bias[n * 64 + d4];
        float* pa = &QA[i * 66 + d4];
        *(float2*)&pa[0] = make_float2(q4.x + rr.x, q4.y + rr.y);
        *(float2*)&pa[2] = make_float2(q4.z + rr.z, q4.w + rr.w);
    }
    load_tiles(0, vs0A);
    cp_commit();
    cp_wait0();
    __syncthreads();

    float m_r[8], l_r[8];
    ull acc2[8][2];
    #pragma unroll
    for (int r = 0; r < 8; r++) {
        m_r[r] = -INFINITY; l_r[r] = 0.f;
        acc2[r][0] = 0ULL; acc2[r][1] = 0ULL;
    }

    const float* pQA = QA + ty * 66;
    const float* pK  = Ks + tx * 66;
    const float* pRB = RB + (tx - ty + 15) * 66;
    const float* pRE = RE + (ty - tx + 15) * 66;

    for (int jt = 0; jt < 16; jt++) {
        const int j0 = jt * 64;
        const float* Vsb = (jt & 1) ? Vs1 : Vs0;
        const uint32_t vsNext = (jt & 1) ? vs0A : vs1A;

        float db[11];
        {
            const float* pD = relD + (1024 + j0 - i0 + tx - ty - 112);
            #pragma unroll
            for (int m = 0; m < 11; m++) db[m] = pD[16 * m];
        }

        ull s2[8][4];
        #pragma unroll
        for (int r = 0; r < 8; r++)
            #pragma unroll
            for (int c = 0; c < 4; c++) s2[r][c] = 0ULL;

        #pragma unroll 2
        for (int d = 0; d < 64; d += 2) {
            ull qa[8], k2[4], rb[11], re[11];
            #pragma unroll
            for (int r = 0; r < 8; r++) qa[r] = *(const ull*)&pQA[r * 1056 + d];
            #pragma unroll
            for (int c = 0; c < 4; c++) k2[c] = *(const ull*)&pK[c * 1056 + d];
            #pragma unroll
            for (int m = 0; m < 11; m++) {
                rb[m] = *(const ull*)&pRB[m * 1056 + d];
                re[m] = *(const ull*)&pRE[m * 1056 + d];
            }
            #pragma unroll
            for (int r = 0; r < 8; r++)
                #pragma unroll
                for (int c = 0; c < 4; c++) {
                    ull v = fma2(qa[r], k2[c], s2[r][c]);
                    v = fma2(qa[r], rb[c - r + 7], v);
                    s2[r][c] = fma2(k2[c], re[r - c + 3], v);
                }
        }
        __syncthreads();   // SYNC1: all warps done reading Ks/RB/RE

        if (jt < 15) {
            load_tiles(j0 + 64, vsNext);
            cp_commit();
        }

        float s[8][4];
        #pragma unroll
        for (int r = 0; r < 8; r++)
            #pragma unroll
            for (int c = 0; c < 4; c++) {
                float2 v = unpack2(s2[r][c]);
                s[r][c] = v.x + v.y + db[c - r + 7];
            }

        #pragma unroll
        for (int c = 0; c < 4; c++) {
            if (j0 + tx + 16 * c >= seq) {
                #pragma unroll
                for (int r = 0; r < 8; r++) s[r][c] = -1e30f;
            }
        }
        #pragma unroll
        for (int r = 0; r < 8; r++) {
            float mr = fmaxf(fmaxf(s[r][0], s[r][1]), fmaxf(s[r][2], s[r][3]));
            mr = fmaxf(mr, __shfl_xor_sync(0xffffffffu, mr, 1));
            mr = fmaxf(mr, __shfl_xor_sync(0xffffffffu, mr, 2));
            mr = fmaxf(mr, __shfl_xor_sync(0xffffffffu, mr, 4));
            mr = fmaxf(mr, __shfl_xor_sync(0xffffffffu, mr, 8));
            float mnew = fmaxf(m_r[r], mr);
            float scale = __expf(m_r[r] - mnew);
            float psum = 0.f;
            float* prow = &Pm[(ty + 16 * r) * 66 + tx];
            #pragma unroll
            for (int c = 0; c < 4; c++) {
                float p = __expf(s[r][c] - mnew);
                prow[16 * c] = p;
                psum += p;
            }
            psum += __shfl_xor_sync(0xffffffffu, psum, 1);
            psum += __shfl_xor_sync(0xffffffffu, psum, 2);
            psum += __shfl_xor_sync(0xffffffffu, psum, 4);
            psum += __shfl_xor_sync(0xffffffffu, psum, 8);
            l_r[r] = l_r[r] * scale + psum;
            m_r[r] = mnew;
            ull sc2 = pack2(scale, scale);
            acc2[r][0] = mul2(acc2[r][0], sc2);
            acc2[r][1] = mul2(acc2[r][1], sc2);
        }
        __syncwarp(0xffffffffu);

        #pragma unroll 2
        for (int jj = 0; jj < 64; jj += 2) {
            ull v01 = *(const ull*)&Vsb[jj * 64 + tx4];
            ull v23 = *(const ull*)&Vsb[jj * 64 + tx4 + 2];
            ull w01 = *(const ull*)&Vsb[(jj + 1) * 64 + tx4];
            ull w23 = *(const ull*)&Vsb[(jj + 1) * 64 + tx4 + 2];
            #pragma unroll
            for (int r = 0; r < 8; r++) {
                float2 p = *(const float2*)&Pm[(ty + 16 * r) * 66 + jj];
                ull px = pack2(p.x, p.x);
                ull py = pack2(p.y, p.y);
                acc2[r][0] = fma2(px, v01, acc2[r][0]);
                acc2[r][1] = fma2(px, v23, acc2[r][1]);
                acc2[r][0] = fma2(py, w01, acc2[r][0]);
                acc2[r][1] = fma2(py, w23, acc2[r][1]);
            }
        }

        cp_wait0();
        __syncthreads();   // SYNC2
    }

    #pragma unroll
    for (int r = 0; r < 8; r++) {
        float inv = 1.0f / l_r[r];
        float2 a01 = unpack2(acc2[r][0]);
        float2 a23 = unpack2(acc2[r][1]);
        int row = i0 + ty + 16 * r;
        float4 o;
        o.x = a01.x * inv; o.y = a01.y * inv;
        o.z = a23.x * inv; o.w = a23.y * inv;
        *(float4*)&out[(size_t)(b * 1024 + row) * 512 + n * 64 + tx4] = o;
    }
}

// ---------------------------------------------------------------------------
extern "C" void kernel_launch(void* const* d_in, const int* in_sizes, int n_in,
                              void* d_out, int out_size) {
    const float* query    = (const float*)d_in[0];
    const float* key      = (const float*)d_in[1];
    const float* value    = (const float*)d_in[2];
    const float* w_q_w    = (const float*)d_in[3];
    const float* w_q_b    = (const float*)d_in[4];
    const float* w_v_w    = (const float*)d_in[5];
    const float* w_v_b    = (const float*)d_in[6];
    const float* w_r_w    = (const float*)d_in[7];
    const float* w_r_b    = (const float*)d_in[8];
    const float* r_r_bias = (const float*)d_in[9];
    const float* r_w_bias = (const float*)d_in[10];
    const int*   seq_len  = (const int*)d_in[11];
    float* out = (float*)d_out;

    const int rel_smem = (32768 + 4096) * 4;   // 147456
    cudaFuncSetAttribute(rel_kernel, cudaFuncAttributeMaxDynamicSharedMemorySize, rel_smem);
    rel_kernel<<<256, 256, rel_smem>>>(w_r_w, w_r_b);
    reld_kernel<<<64, 256>>>(r_r_bias, r_w_bias);

    proj2_kernel<<<dim3(32, 4, 2), 256>>>(query, value, w_q_w, w_q_b, w_v_w, w_v_b);

    const int attn_smem = 54656 * 4;   // 218624
    cudaFuncSetAttribute(attn_kernel, cudaFuncAttributeMaxDynamicSharedMemorySize, attn_smem);
    attn_kernel<<<dim3(8, 32), 256, attn_smem>>>(key, r_r_bias, seq_len, out);
}